// round 1
// baseline (speedup 1.0000x reference)
#include <cuda_runtime.h>
#include <cuda_bf16.h>
#include <math.h>

#define NB 1024          // fixed grid for pass-1 (partials array size)
#define NT 256           // threads per block
#define C  14            // labels per sample (fixed by problem)

__device__ float g_partials[NB];

// Pass 1: streaming BCE + per-row group masking, block-level partial sums.
__global__ __launch_bounds__(NT) void bce_partial_kernel(
    const float* __restrict__ inputs,
    const float* __restrict__ targets,
    const int*   __restrict__ groups,
    long long B)
{
    // Load the 14 group ids once per thread (L2/L1 resident).
    int g[C];
#pragma unroll
    for (int c = 0; c < C; c++) g[c] = groups[c];

    const long long tasks  = B >> 1;                 // one task = 2 rows = 28 floats
    const long long tid    = (long long)blockIdx.x * blockDim.x + threadIdx.x;
    const long long stride = (long long)gridDim.x * blockDim.x;

    float acc = 0.0f;

    for (long long task = tid; task < tasks; task += stride) {
        const float4* ip = reinterpret_cast<const float4*>(inputs  + task * 28);
        const float4* tp = reinterpret_cast<const float4*>(targets + task * 28);

        float bce[28];
        float s1a = 0.f, s2a = 0.f, s3a = 0.f;   // row 0 group sums (groups 1..3)
        float s1b = 0.f, s2b = 0.f, s3b = 0.f;   // row 1 group sums
        float tv[28];

#pragma unroll
        for (int j = 0; j < 7; j++) {
            float4 xv = ip[j];
            float4 wv = tp[j];
            float xs[4] = {xv.x, xv.y, xv.z, xv.w};
            float ts[4] = {wv.x, wv.y, wv.z, wv.w};
#pragma unroll
            for (int k = 0; k < 4; k++) {
                const int idx = 4 * j + k;       // compile-time
                const int c   = idx % C;         // compile-time
                const int row = idx / C;         // compile-time
                float x = xs[k];
                float t = ts[k];
                tv[idx] = t;
                float a = fabsf(x);
                // BCE with logits: max(x,0) - x*t + log1p(exp(-|x|))
                bce[idx] = fmaxf(x, 0.0f) - x * t + log1pf(__expf(-a));
                // branchless group-sum accumulation
                float add1 = (g[c] == 1) ? t : 0.0f;
                float add2 = (g[c] == 2) ? t : 0.0f;
                float add3 = (g[c] == 3) ? t : 0.0f;
                if (row == 0) { s1a += add1; s2a += add2; s3a += add3; }
                else          { s1b += add1; s2b += add2; s3b += add3; }
            }
        }

        float k1a = (s1a > 0.f) ? 1.f : 0.f;
        float k2a = (s2a > 0.f) ? 1.f : 0.f;
        float k3a = (s3a > 0.f) ? 1.f : 0.f;
        float k1b = (s1b > 0.f) ? 1.f : 0.f;
        float k2b = (s2b > 0.f) ? 1.f : 0.f;
        float k3b = (s3b > 0.f) ? 1.f : 0.f;

#pragma unroll
        for (int idx = 0; idx < 28; idx++) {
            const int c   = idx % C;
            const int row = idx / C;
            float k1 = row ? k1b : k1a;
            float k2 = row ? k2b : k2a;
            float k3 = row ? k3b : k3a;
            float keep = (g[c] == 0) ? 1.0f
                       : (g[c] == 1) ? k1
                       : (g[c] == 2) ? k2
                       : k3;
            acc += bce[idx] * keep;
        }
        (void)tv;
    }

    // Odd-B tail: one thread handles the last row scalar.
    if ((B & 1) && tid == 0) {
        const float* xr = inputs  + (B - 1) * C;
        const float* tr = targets + (B - 1) * C;
        float s1 = 0.f, s2 = 0.f, s3 = 0.f;
        float bce[C];
#pragma unroll
        for (int c = 0; c < C; c++) {
            float x = xr[c], t = tr[c];
            bce[c] = fmaxf(x, 0.0f) - x * t + log1pf(__expf(-fabsf(x)));
            s1 += (g[c] == 1) ? t : 0.f;
            s2 += (g[c] == 2) ? t : 0.f;
            s3 += (g[c] == 3) ? t : 0.f;
        }
        float k1 = (s1 > 0.f) ? 1.f : 0.f;
        float k2 = (s2 > 0.f) ? 1.f : 0.f;
        float k3 = (s3 > 0.f) ? 1.f : 0.f;
#pragma unroll
        for (int c = 0; c < C; c++) {
            float keep = (g[c] == 0) ? 1.0f
                       : (g[c] == 1) ? k1
                       : (g[c] == 2) ? k2
                       : k3;
            acc += bce[c] * keep;
        }
    }

    // Block reduction (deterministic).
    __shared__ float sh[NT];
    sh[threadIdx.x] = acc;
    __syncthreads();
#pragma unroll
    for (int s = NT / 2; s > 0; s >>= 1) {
        if (threadIdx.x < s) sh[threadIdx.x] += sh[threadIdx.x + s];
        __syncthreads();
    }
    if (threadIdx.x == 0) g_partials[blockIdx.x] = sh[0];
}

// Pass 2: single block reduces the NB partials and writes the mean.
__global__ __launch_bounds__(NB) void bce_final_kernel(float* __restrict__ out,
                                                       float inv_count)
{
    __shared__ float sh[NB];
    sh[threadIdx.x] = g_partials[threadIdx.x];
    __syncthreads();
#pragma unroll
    for (int s = NB / 2; s > 0; s >>= 1) {
        if (threadIdx.x < s) sh[threadIdx.x] += sh[threadIdx.x + s];
        __syncthreads();
    }
    if (threadIdx.x == 0) out[0] = sh[0] * inv_count;
}

extern "C" void kernel_launch(void* const* d_in, const int* in_sizes, int n_in,
                              void* d_out, int out_size)
{
    const float* inputs  = (const float*)d_in[0];
    const float* targets = (const float*)d_in[1];
    const int*   groups  = (const int*)d_in[2];
    float*       out     = (float*)d_out;

    long long B = (long long)in_sizes[0] / C;
    float inv_count = 1.0f / ((float)B * (float)C);

    bce_partial_kernel<<<NB, NT>>>(inputs, targets, groups, B);
    bce_final_kernel<<<1, NB>>>(out, inv_count);
}

// round 2
// speedup vs baseline: 1.4391x; 1.4391x over previous
#include <cuda_runtime.h>
#include <math.h>

#define NB 2048          // grid size (partials array size)
#define NT 256           // threads per block
#define C  14            // labels per sample

__device__ float g_partials[NB];
__device__ unsigned int g_done;   // zero-init; wraps back to 0 every launch

// Expected (dataset) group assignment; fast path is specialized on it and
// verified at runtime. Generic fallback handles any other assignment.
// groups = [0,1,1,2,2,0,3,3,1,2,0,3,1,2]
//   group0: {0,5,10}  group1: {1,2,8,12}  group2: {3,4,9,13}  group3: {6,7,11}

__device__ __forceinline__ float bce_elem(float x, float t) {
    // max(x,0) - x*t + log1p(exp(-|x|))  ==  x*(1-t) + log(1+exp(-x))
    return fmaf(-x, t, x) + __logf(1.0f + __expf(-x));
}

// Generic single-row loss with runtime groups (cold path / odd tail).
__device__ float generic_row(const float* xr, const float* tr, const int* g) {
    float b[C], ts[4] = {0.f, 0.f, 0.f, 0.f};
#pragma unroll
    for (int c = 0; c < C; c++) {
        float x = xr[c], t = tr[c];
        float ax = fabsf(x);
        b[c] = fmaxf(x, 0.0f) - x * t + log1pf(expf(-ax));
#pragma unroll
        for (int j = 1; j < 4; j++) ts[j] += (g[c] == j) ? t : 0.f;
    }
    float row = 0.f;
#pragma unroll
    for (int c = 0; c < C; c++) {
        int gc = g[c];
        float keep = (gc == 0) ? 1.f : ((ts[gc] > 0.f) ? 1.f : 0.f);
        row += b[c] * keep;
    }
    return row;
}

__global__ __launch_bounds__(NT) void bce_fused_kernel(
    const float* __restrict__ inputs,
    const float* __restrict__ targets,
    const int*   __restrict__ groups,
    float* __restrict__ out,
    long long B, float inv_count)
{
    const int EXP[C] = {0, 1, 1, 2, 2, 0, 3, 3, 1, 2, 0, 3, 1, 2};
    int g[C];
    bool fast = true;
#pragma unroll
    for (int c = 0; c < C; c++) { g[c] = groups[c]; fast &= (g[c] == EXP[c]); }

    const long long tasks  = B >> 1;                 // 1 task = 2 rows = 7 float4
    const long long tid    = (long long)blockIdx.x * NT + threadIdx.x;
    const long long stride = (long long)NB * NT;

    float acc = 0.0f;

    if (fast) {
        for (long long task = tid; task < tasks; task += stride) {
            const float4* ip = reinterpret_cast<const float4*>(inputs  + task * 28);
            const float4* tp = reinterpret_cast<const float4*>(targets + task * 28);
            float4 xv[7], tv[7];
#pragma unroll
            for (int j = 0; j < 7; j++) { xv[j] = __ldcs(ip + j); tv[j] = __ldcs(tp + j); }

            float x[28], t[28];
#pragma unroll
            for (int j = 0; j < 7; j++) {
                x[4*j+0] = xv[j].x; x[4*j+1] = xv[j].y; x[4*j+2] = xv[j].z; x[4*j+3] = xv[j].w;
                t[4*j+0] = tv[j].x; t[4*j+1] = tv[j].y; t[4*j+2] = tv[j].z; t[4*j+3] = tv[j].w;
            }

#pragma unroll
            for (int r = 0; r < 2; r++) {
                const int o = r * C;
                float b[C];
#pragma unroll
                for (int c = 0; c < C; c++) b[c] = bce_elem(x[o + c], t[o + c]);

                // compile-time group add trees (pattern verified above)
                float S0 = (b[0] + b[5]) + b[10];
                float S1 = (b[1] + b[2]) + (b[8] + b[12]);
                float S2 = (b[3] + b[4]) + (b[9] + b[13]);
                float S3 = (b[6] + b[7]) + b[11];
                float T1 = (t[o+1] + t[o+2]) + (t[o+8] + t[o+12]);
                float T2 = (t[o+3] + t[o+4]) + (t[o+9] + t[o+13]);
                float T3 = (t[o+6] + t[o+7]) + t[o+11];

                float row = S0;
                row += (T1 > 0.f) ? S1 : 0.f;
                row += (T2 > 0.f) ? S2 : 0.f;
                row += (T3 > 0.f) ? S3 : 0.f;
                acc += row;
            }
        }
    } else {
        // generic fallback: one row per thread (cold path, still correct)
        for (long long row = tid; row < B; row += stride)
            acc += generic_row(inputs + row * C, targets + row * C, g);
    }

    // odd-B tail (fast path only covers 2*tasks rows)
    if (fast && (B & 1) && tid == 0)
        acc += generic_row(inputs + (B - 1) * C, targets + (B - 1) * C, g);

    // ---- block reduction ----
    __shared__ float warp_s[NT / 32];
    __shared__ bool amLast;
    float v = acc;
#pragma unroll
    for (int o = 16; o > 0; o >>= 1) v += __shfl_down_sync(0xffffffffu, v, o);
    if ((threadIdx.x & 31) == 0) warp_s[threadIdx.x >> 5] = v;
    __syncthreads();

    if (threadIdx.x == 0) {
        float s = 0.f;
#pragma unroll
        for (int i = 0; i < NT / 32; i++) s += warp_s[i];
        g_partials[blockIdx.x] = s;
        __threadfence();
        unsigned int d = atomicInc(&g_done, NB - 1);   // wraps to 0 on last arrival
        amLast = (d == NB - 1);
    }
    __syncthreads();

    // ---- last block finishes the mean (deterministic fixed-order sum) ----
    if (amLast) {
        float s = 0.f;
        for (int i = threadIdx.x; i < NB; i += NT) s += g_partials[i];
#pragma unroll
        for (int o = 16; o > 0; o >>= 1) s += __shfl_down_sync(0xffffffffu, s, o);
        __syncthreads();                      // warp_s reuse barrier
        if ((threadIdx.x & 31) == 0) warp_s[threadIdx.x >> 5] = s;
        __syncthreads();
        if (threadIdx.x == 0) {
            float total = 0.f;
#pragma unroll
            for (int i = 0; i < NT / 32; i++) total += warp_s[i];
            out[0] = total * inv_count;
        }
    }
}

extern "C" void kernel_launch(void* const* d_in, const int* in_sizes, int n_in,
                              void* d_out, int out_size)
{
    const float* inputs  = (const float*)d_in[0];
    const float* targets = (const float*)d_in[1];
    const int*   groups  = (const int*)d_in[2];
    float*       out     = (float*)d_out;

    long long B = (long long)in_sizes[0] / C;
    float inv_count = (float)(1.0 / ((double)B * (double)C));

    bce_fused_kernel<<<NB, NT>>>(inputs, targets, groups, out, B, inv_count);
}

// round 3
// speedup vs baseline: 1.7916x; 1.2449x over previous
#include <cuda_runtime.h>
#include <math.h>
#include <stdint.h>

#define C        14
#define NT       256            // threads per block
#define TILE     256            // tasks per tile (1 task = 2 rows = 112 B)
#define NSTAGES  3
#define GRID     148            // persistent blocks (1/SM)

#define TASK_BYTES   112                      // 28 floats
#define ARR_BYTES    (TILE * TASK_BYTES)      // 28672 per array per stage
#define STAGE_BYTES  (2 * ARR_BYTES)          // 57344
#define MBAR_OFF     (NSTAGES * STAGE_BYTES)  // 172032
#define SMEM_BYTES   (MBAR_OFF + 2 * NSTAGES * 8)

__device__ float g_partials[GRID];
__device__ unsigned int g_done;   // wraps to 0 each launch

// ---------------- mbarrier / TMA helpers ----------------
__device__ __forceinline__ uint32_t smem_u32(const void* p) {
    uint32_t a;
    asm("{ .reg .u64 t; cvta.to.shared.u64 t, %1; cvt.u32.u64 %0, t; }" : "=r"(a) : "l"(p));
    return a;
}
__device__ __forceinline__ void mbar_init(uint32_t m, uint32_t cnt) {
    asm volatile("mbarrier.init.shared.b64 [%0], %1;" :: "r"(m), "r"(cnt) : "memory");
}
__device__ __forceinline__ void mbar_arrive(uint32_t m) {
    asm volatile("mbarrier.arrive.shared.b64 _, [%0];" :: "r"(m) : "memory");
}
__device__ __forceinline__ void mbar_expect_tx(uint32_t m, uint32_t bytes) {
    asm volatile("mbarrier.arrive.expect_tx.shared.b64 _, [%0], %1;" :: "r"(m), "r"(bytes) : "memory");
}
__device__ __forceinline__ void mbar_wait(uint32_t m, uint32_t parity) {
    uint32_t done;
    asm volatile(
        "{\n\t.reg .pred p;\n\t"
        "mbarrier.try_wait.parity.acquire.cta.shared::cta.b64 p, [%1], %2;\n\t"
        "selp.b32 %0, 1, 0, p;\n\t}"
        : "=r"(done) : "r"(m), "r"(parity) : "memory");
    if (!done) {
        asm volatile(
            "{\n\t.reg .pred P1;\n"
            "W_%=:\n\t"
            "mbarrier.try_wait.parity.acquire.cta.shared::cta.b64 P1, [%0], %1, 0x989680;\n\t"
            "@P1 bra D_%=;\n\t"
            "bra W_%=;\n"
            "D_%=:\n\t}"
            :: "r"(m), "r"(parity) : "memory");
    }
}
__device__ __forceinline__ void bulk_g2s(uint32_t dst, const void* src, uint32_t bytes, uint32_t mbar) {
    asm volatile(
        "cp.async.bulk.shared::cta.global.mbarrier::complete_tx::bytes [%0], [%1], %2, [%3];"
        :: "r"(dst), "l"(src), "r"(bytes), "r"(mbar) : "memory");
}
// --------------------------------------------------------

__device__ __forceinline__ float bce_elem(float x, float t) {
    return fmaf(-x, t, x) + __logf(1.0f + __expf(-x));
}

__device__ float generic_row(const float* xr, const float* tr, const int* g) {
    float b[C], ts[4] = {0.f, 0.f, 0.f, 0.f};
#pragma unroll
    for (int c = 0; c < C; c++) {
        float x = xr[c], t = tr[c];
        b[c] = fmaxf(x, 0.0f) - x * t + log1pf(expf(-fabsf(x)));
#pragma unroll
        for (int j = 1; j < 4; j++) ts[j] += (g[c] == j) ? t : 0.f;
    }
    float row = 0.f;
#pragma unroll
    for (int c = 0; c < C; c++) {
        int gc = g[c];
        row += b[c] * ((gc == 0) ? 1.f : ((ts[gc] > 0.f) ? 1.f : 0.f));
    }
    return row;
}

// Fast-path math on one staged task (2 rows, 28 floats each array).
__device__ __forceinline__ float task_loss(const float4* xp, const float4* tp) {
    float x[28], t[28];
#pragma unroll
    for (int j = 0; j < 7; j++) {
        float4 xv = xp[j], tv = tp[j];
        x[4*j+0] = xv.x; x[4*j+1] = xv.y; x[4*j+2] = xv.z; x[4*j+3] = xv.w;
        t[4*j+0] = tv.x; t[4*j+1] = tv.y; t[4*j+2] = tv.z; t[4*j+3] = tv.w;
    }
    float acc = 0.f;
#pragma unroll
    for (int r = 0; r < 2; r++) {
        const int o = r * C;
        float b[C];
#pragma unroll
        for (int c = 0; c < C; c++) b[c] = bce_elem(x[o + c], t[o + c]);
        float S0 = (b[0] + b[5]) + b[10];
        float S1 = (b[1] + b[2]) + (b[8] + b[12]);
        float S2 = (b[3] + b[4]) + (b[9] + b[13]);
        float S3 = (b[6] + b[7]) + b[11];
        float T1 = (t[o+1] + t[o+2]) + (t[o+8] + t[o+12]);
        float T2 = (t[o+3] + t[o+4]) + (t[o+9] + t[o+13]);
        float T3 = (t[o+6] + t[o+7]) + t[o+11];
        float row = S0;
        row += (T1 > 0.f) ? S1 : 0.f;
        row += (T2 > 0.f) ? S2 : 0.f;
        row += (T3 > 0.f) ? S3 : 0.f;
        acc += row;
    }
    return acc;
}

__global__ __launch_bounds__(NT) void bce_tma_kernel(
    const float* __restrict__ inputs,
    const float* __restrict__ targets,
    const int*   __restrict__ groups,
    float* __restrict__ out,
    long long B, float inv_count)
{
    extern __shared__ char smem[];
    const int tid = threadIdx.x;

    const int EXP[C] = {0, 1, 1, 2, 2, 0, 3, 3, 1, 2, 0, 3, 1, 2};
    int g[C];
    bool fast = true;
#pragma unroll
    for (int c = 0; c < C; c++) { g[c] = groups[c]; fast &= (g[c] == EXP[c]); }

    const long long tasks  = B >> 1;
    float acc = 0.0f;

    if (fast) {
        const uint32_t sbase = smem_u32(smem);
        const uint32_t full0  = sbase + MBAR_OFF;
        const uint32_t empty0 = sbase + MBAR_OFF + NSTAGES * 8;

        if (tid == 0) {
#pragma unroll
            for (int s = 0; s < NSTAGES; s++) {
                mbar_init(full0  + s * 8, 1);
                mbar_init(empty0 + s * 8, NT);
            }
        }
        asm volatile("fence.proxy.async.shared::cta;" ::: "memory");
        __syncthreads();

        const long long ntiles = (tasks + TILE - 1) / TILE;
        // local tile k -> global tile id = blockIdx.x + k*GRID
        long long nlocal = 0;
        if ((long long)blockIdx.x < ntiles)
            nlocal = (ntiles - 1 - blockIdx.x) / GRID + 1;

        // producer cursor (thread 0 only uses it)
        int ps = 0; uint32_t pp = 1;
        // consumer cursor
        int cs = 0; uint32_t cp = 0;

        // prologue: fill pipeline
        if (tid == 0) {
            long long npro = nlocal < NSTAGES ? nlocal : NSTAGES;
            for (long long k = 0; k < npro; k++) {
                long long tileId = blockIdx.x + k * GRID;
                long long base   = tileId * TILE;
                uint32_t ntsk    = (uint32_t)((tasks - base) < TILE ? (tasks - base) : TILE);
                uint32_t bytes   = ntsk * TASK_BYTES;
                mbar_wait(empty0 + ps * 8, pp);                 // passes immediately 1st round
                mbar_expect_tx(full0 + ps * 8, 2 * bytes);
                uint32_t dst = sbase + ps * STAGE_BYTES;
                bulk_g2s(dst,             inputs  + base * 28, bytes, full0 + ps * 8);
                bulk_g2s(dst + ARR_BYTES, targets + base * 28, bytes, full0 + ps * 8);
                if (++ps == NSTAGES) { ps = 0; pp ^= 1; }
            }
        }

        for (long long k = 0; k < nlocal; k++) {
            long long tileId = blockIdx.x + k * GRID;
            long long base   = tileId * TILE;
            long long ntsk   = (tasks - base) < TILE ? (tasks - base) : TILE;

            mbar_wait(full0 + cs * 8, cp);

            if (tid < ntsk) {
                const char* st = smem + cs * STAGE_BYTES + tid * TASK_BYTES;
                acc += task_loss((const float4*)st,
                                 (const float4*)(st + ARR_BYTES));
            }
            mbar_arrive(empty0 + cs * 8);

            if (tid == 0 && k + NSTAGES < nlocal) {
                long long t2    = blockIdx.x + (k + NSTAGES) * GRID;
                long long b2    = t2 * TILE;
                uint32_t  n2    = (uint32_t)((tasks - b2) < TILE ? (tasks - b2) : TILE);
                uint32_t  by2   = n2 * TASK_BYTES;
                mbar_wait(empty0 + ps * 8, pp);
                mbar_expect_tx(full0 + ps * 8, 2 * by2);
                uint32_t dst = sbase + ps * STAGE_BYTES;
                bulk_g2s(dst,             inputs  + b2 * 28, by2, full0 + ps * 8);
                bulk_g2s(dst + ARR_BYTES, targets + b2 * 28, by2, full0 + ps * 8);
                if (++ps == NSTAGES) { ps = 0; pp ^= 1; }
            }
            if (++cs == NSTAGES) { cs = 0; cp ^= 1; }
        }

        // odd-B tail row
        if ((B & 1) && blockIdx.x == 0 && tid == 0)
            acc += generic_row(inputs + (B - 1) * C, targets + (B - 1) * C, g);
    } else {
        // generic fallback (cold, correct for any groups)
        const long long gtid   = (long long)blockIdx.x * NT + tid;
        const long long stride = (long long)GRID * NT;
        for (long long row = gtid; row < B; row += stride)
            acc += generic_row(inputs + row * C, targets + row * C, g);
    }

    // ---- block reduction ----
    __shared__ float warp_s[NT / 32];
    __shared__ bool amLast;
    float v = acc;
#pragma unroll
    for (int o = 16; o > 0; o >>= 1) v += __shfl_down_sync(0xffffffffu, v, o);
    if ((tid & 31) == 0) warp_s[tid >> 5] = v;
    __syncthreads();

    if (tid == 0) {
        float s = 0.f;
#pragma unroll
        for (int i = 0; i < NT / 32; i++) s += warp_s[i];
        g_partials[blockIdx.x] = s;
        __threadfence();
        unsigned int d = atomicInc(&g_done, GRID - 1);
        amLast = (d == GRID - 1);
    }
    __syncthreads();

    if (amLast) {
        float s = 0.f;
        for (int i = tid; i < GRID; i += NT) s += g_partials[i];
#pragma unroll
        for (int o = 16; o > 0; o >>= 1) s += __shfl_down_sync(0xffffffffu, s, o);
        __syncthreads();
        if ((tid & 31) == 0) warp_s[tid >> 5] = s;
        __syncthreads();
        if (tid == 0) {
            float total = 0.f;
#pragma unroll
            for (int i = 0; i < NT / 32; i++) total += warp_s[i];
            out[0] = total * inv_count;
        }
    }
}

extern "C" void kernel_launch(void* const* d_in, const int* in_sizes, int n_in,
                              void* d_out, int out_size)
{
    const float* inputs  = (const float*)d_in[0];
    const float* targets = (const float*)d_in[1];
    const int*   groups  = (const int*)d_in[2];
    float*       out     = (float*)d_out;

    long long B = (long long)in_sizes[0] / C;
    float inv_count = (float)(1.0 / ((double)B * (double)C));

    static bool attr_set = false;
    if (!attr_set) {
        cudaFuncSetAttribute(bce_tma_kernel,
                             cudaFuncAttributeMaxDynamicSharedMemorySize, SMEM_BYTES);
        attr_set = true;
    }
    bce_tma_kernel<<<GRID, NT, SMEM_BYTES>>>(inputs, targets, groups, out, B, inv_count);
}